// round 11
// baseline (speedup 1.0000x reference)
#include <cuda_runtime.h>
#include <cuda_bf16.h>
#include <cstdint>
#include <math.h>

#define NB    2
#define CIN   320
#define COUT  160
#define S_TOT 131072
#define BM    64           // spatial tile per CTA
#define BK    32           // k chunk
#define NCHUNK (CIN / BK)  // 10

// ---------------- scratch (device globals) ---------------------------------
__device__ float d_y[2][(size_t)NB * COUT * S_TOT];   // [conv][n][co][s]
__device__ float d_sum[2 * NB * COUT];
__device__ float d_sumsq[2 * NB * COUT];
__device__ float d_mu[2 * NB * COUT];
__device__ float d_istd[2 * NB * COUT];
// prepacked W: per (conv,chunk): hi[160*80B] | lo[160*80B] (padded smem image)
#define WPACK_PER 25600
__device__ __align__(16) unsigned char d_Wpack[2 * NCHUNK * WPACK_PER];

// ---------------- helpers ---------------------------------------------------
__device__ __forceinline__ uint32_t smem_u32(const void* p) {
    uint32_t a;
    asm("{ .reg .u64 t; cvta.to.shared.u64 t, %1; cvt.u32.u64 %0, t; }" : "=r"(a) : "l"(p));
    return a;
}
__device__ __forceinline__ void ldsm_x4(uint32_t* r, uint32_t addr) {
    asm volatile("ldmatrix.sync.aligned.m8n8.x4.shared.b16 {%0,%1,%2,%3}, [%4];"
                 : "=r"(r[0]), "=r"(r[1]), "=r"(r[2]), "=r"(r[3]) : "r"(addr));
}
__device__ __forceinline__ void ldsm_x2(uint32_t* r, uint32_t addr) {
    asm volatile("ldmatrix.sync.aligned.m8n8.x2.shared.b16 {%0,%1}, [%2];"
                 : "=r"(r[0]), "=r"(r[1]) : "r"(addr));
}
__device__ __forceinline__ void mma16816(float* d, const uint32_t* a, const uint32_t* b) {
    asm volatile("mma.sync.aligned.m16n8k16.row.col.f32.bf16.bf16.f32 "
                 "{%0,%1,%2,%3}, {%4,%5,%6,%7}, {%8,%9}, {%0,%1,%2,%3};"
                 : "+f"(d[0]), "+f"(d[1]), "+f"(d[2]), "+f"(d[3])
                 : "r"(a[0]), "r"(a[1]), "r"(a[2]), "r"(a[3]), "r"(b[0]), "r"(b[1]));
}
__device__ __forceinline__ uint32_t pack_hi(float v0, float v1, uint32_t& lo) {
    __nv_bfloat16 h0 = __float2bfloat16(v0);
    __nv_bfloat16 h1 = __float2bfloat16(v1);
    float r0 = v0 - __bfloat162float(h0);
    float r1 = v1 - __bfloat162float(h1);
    __nv_bfloat162 L = __halves2bfloat162(__float2bfloat16(r0), __float2bfloat16(r1));
    lo = *(uint32_t*)&L;
    __nv_bfloat162 H = __halves2bfloat162(h0, h1);
    return *(uint32_t*)&H;
}
__device__ __forceinline__ void cp_async16(uint32_t saddr, const void* g) {
    asm volatile("cp.async.cg.shared.global [%0], [%1], 16;" :: "r"(saddr), "l"(g) : "memory");
}
#define CP_COMMIT() asm volatile("cp.async.commit_group;" ::: "memory")
#define CP_WAIT0()  asm volatile("cp.async.wait_group 0;" ::: "memory")

// smem layout (dynamic):
//   A buf0 [hi 5120 | lo 5120] | A buf1 [hi | lo] | B buf0 [25600] | B buf1 [25600]
#define ABUF_STRIDE 10240
#define ALO_REL     5120
#define B0_OFF      20480
#define B1_OFF      46080
#define SMEM_BYTES  71680
#define BLO_REL     12800   // lo block inside a B buffer

// ---------------------------------------------------------------------------
__global__ void zero_stats() {
    int i = blockIdx.x * blockDim.x + threadIdx.x;
    if (i < 2 * NB * COUT) { d_sum[i] = 0.f; d_sumsq[i] = 0.f; }
}

// Pack Wg/Wx into padded bf16 hi/lo smem images
__global__ void prepack_W(const float* __restrict__ Wg, const float* __restrict__ Wx) {
    int i = blockIdx.x * blockDim.x + threadIdx.x;
    if (i >= 2 * NCHUNK * COUT * 20) return;
    int conv  = i / (NCHUNK * COUT * 20);
    int r     = i % (NCHUNK * COUT * 20);
    int chunk = r / (COUT * 20);
    int r2    = r % (COUT * 20);
    int co    = r2 / 20;
    int wp    = r2 % 20;           // 4-byte word within 80B row
    float v0 = 0.f, v1 = 0.f;
    if (wp < 16) {
        const float* W = conv ? Wx : Wg;
        int k = chunk * BK + 2 * wp;
        v0 = W[co * CIN + k];
        v1 = W[co * CIN + k + 1];
    }
    uint32_t lo, hi = pack_hi(v0, v1, lo);
    size_t base = (size_t)(conv * NCHUNK + chunk) * WPACK_PER;
    *(uint32_t*)(d_Wpack + base + co * 80 + wp * 4)           = hi;
    *(uint32_t*)(d_Wpack + base + BLO_REL + co * 80 + wp * 4) = lo;
}

// ---------------------------------------------------------------------------
// mma.sync GEMM, tile 64x160, 2 CTAs/SM, double-buffered A+B.
// Schedule per chunk: commit B(c+1) | STS A(c+1) | LDG A(c+2) | compute(c)
//                     | cp.wait0 | __syncthreads  (wait BEFORE barrier -> all
//                     threads' copy portions visible; fixes round-7 race)
__global__ __launch_bounds__(256, 2)
void gemm_mma(const float* __restrict__ X, const float* __restrict__ bias, int conv)
{
    extern __shared__ __align__(16) unsigned char smem_[];
    const uint32_t sb = smem_u32(smem_);

    const int tid  = threadIdx.x;
    const int lane = tid & 31;
    const int warp = tid >> 5;
    const int wm   = warp & 1;   // 2 warps along M (32 rows each)
    const int wn   = warp >> 1;  // 4 warps along N (40 cols each)
    const int n    = blockIdx.y;
    const int s0   = blockIdx.x * BM;
    const float* Xn = X + (size_t)n * CIN * S_TOT;
    const unsigned char* Wb = d_Wpack + (size_t)conv * NCHUNK * WPACK_PER;

    // A prefetch coords: each thread: 8 consecutive k rows at one s
    const int sloc = tid & 63;
    const int kb   = tid >> 6;   // 0..3 (blocks of 8 k)
    const float* asrc0 = Xn + (size_t)(kb * 8) * S_TOT + s0 + sloc;
    const uint32_t aoff = sloc * 80 + kb * 16;

    float acc[2][5][4];
#pragma unroll
    for (int mt = 0; mt < 2; mt++)
#pragma unroll
        for (int nt = 0; nt < 5; nt++)
#pragma unroll
            for (int q = 0; q < 4; q++) acc[mt][nt][q] = 0.f;

    float v[8];
    // ---- prologue: B0 copy; chunk0 -> A buf0; chunk1 -> regs; drain; bar
#pragma unroll
    for (int j = 0; j < 8; j++) v[j] = asrc0[(size_t)j * S_TOT];
    {
#pragma unroll
        for (int i = 0; i < 7; i++) {
            int idx = tid + i * 256;
            if (idx < 1600) cp_async16(sb + B0_OFF + idx * 16, Wb + idx * 16);
        }
        CP_COMMIT();
    }
    {
        uint32_t hw[4], lw[4];
#pragma unroll
        for (int j = 0; j < 4; j++) hw[j] = pack_hi(v[2 * j], v[2 * j + 1], lw[j]);
        *(uint4*)(smem_ + aoff)           = make_uint4(hw[0], hw[1], hw[2], hw[3]);
        *(uint4*)(smem_ + ALO_REL + aoff) = make_uint4(lw[0], lw[1], lw[2], lw[3]);
    }
    {
        const float* asrc = asrc0 + (size_t)BK * S_TOT;
#pragma unroll
        for (int j = 0; j < 8; j++) v[j] = asrc[(size_t)j * S_TOT];
    }
    CP_WAIT0();
    __syncthreads();

    for (int c = 0; c < NCHUNK; c++) {
        // ---- start B copy for chunk c+1 (overlaps the whole compute phase)
        if (c + 1 < NCHUNK) {
            const unsigned char* src = Wb + (size_t)(c + 1) * WPACK_PER;
            uint32_t dstb = sb + (((c + 1) & 1) ? B1_OFF : B0_OFF);
#pragma unroll
            for (int i = 0; i < 7; i++) {
                int idx = tid + i * 256;
                if (idx < 1600) cp_async16(dstb + idx * 16, src + idx * 16);
            }
            CP_COMMIT();
        }
        // ---- convert regs (chunk c+1) into idle A buffer
        if (c + 1 < NCHUNK) {
            uint32_t hw[4], lw[4];
#pragma unroll
            for (int j = 0; j < 4; j++) hw[j] = pack_hi(v[2 * j], v[2 * j + 1], lw[j]);
            uint32_t o = ((c + 1) & 1) * ABUF_STRIDE + aoff;
            *(uint4*)(smem_ + o)           = make_uint4(hw[0], hw[1], hw[2], hw[3]);
            *(uint4*)(smem_ + ALO_REL + o) = make_uint4(lw[0], lw[1], lw[2], lw[3]);
        }
        // ---- LDG chunk c+2 into regs
        if (c + 2 < NCHUNK) {
            const float* asrc = asrc0 + (size_t)(c + 2) * BK * S_TOT;
#pragma unroll
            for (int j = 0; j < 8; j++) v[j] = asrc[(size_t)j * S_TOT];
        }

        // ---- compute chunk c (A[c&1], B[c&1] guaranteed by prev wait+bar)
        const uint32_t Ab = sb + (c & 1) * ABUF_STRIDE;
        const uint32_t Bb = sb + ((c & 1) ? B1_OFF : B0_OFF);
#pragma unroll
        for (int ks = 0; ks < 2; ks++) {
            uint32_t aH[2][4], aL[2][4];
            const uint32_t arow = wm * 32 + (lane & 15);
            const uint32_t acol = ks * 32 + (lane >> 4) * 16;
#pragma unroll
            for (int mt = 0; mt < 2; mt++) {
                uint32_t addr = (arow + mt * 16) * 80 + acol;
                ldsm_x4(aH[mt], Ab + addr);
                ldsm_x4(aL[mt], Ab + ALO_REL + addr);
            }
            const uint32_t brow0 = wn * 40 + (lane >> 4) * 8 + (lane & 7);
            const uint32_t bcol  = ks * 32 + ((lane >> 3) & 1) * 16;
#pragma unroll
            for (int p = 0; p < 2; p++) {   // n-tiles 0..3
                uint32_t bH[4], bL[4];
                uint32_t addr = (brow0 + p * 16) * 80 + bcol;
                ldsm_x4(bH, Bb + addr);
                ldsm_x4(bL, Bb + BLO_REL + addr);
#pragma unroll
                for (int h = 0; h < 2; h++) {
                    int nt = 2 * p + h;
#pragma unroll
                    for (int mt = 0; mt < 2; mt++) {
                        mma16816(acc[mt][nt], aH[mt], bH + 2 * h);
                        mma16816(acc[mt][nt], aL[mt], bH + 2 * h);
                        mma16816(acc[mt][nt], aH[mt], bL + 2 * h);
                    }
                }
            }
            {   // n-tile 4 (last 8 cols) via ldmatrix.x2
                uint32_t bH[2], bL[2];
                uint32_t addr = (wn * 40 + 32 + (lane & 7)) * 80
                              + ks * 32 + ((lane >> 3) & 1) * 16;
                ldsm_x2(bH, Bb + addr);
                ldsm_x2(bL, Bb + BLO_REL + addr);
#pragma unroll
                for (int mt = 0; mt < 2; mt++) {
                    mma16816(acc[mt][4], aH[mt], bH);
                    mma16816(acc[mt][4], aL[mt], bH);
                    mma16816(acc[mt][4], aH[mt], bL);
                }
            }
        }
        // ---- drain this thread's B(c+1) copy, then publish to all threads
        if (c + 1 < NCHUNK) { CP_WAIT0(); }
        __syncthreads();
    }

    // ---- epilogue: +bias, store y[co][s], per-co sum/sumsq atomics
    float* ybase = d_y[conv] + (size_t)n * COUT * S_TOT;
    const int statbase = conv * NB * COUT + n * COUT;
    const int r0 = s0 + wm * 32 + (lane >> 2);
#pragma unroll
    for (int nt = 0; nt < 5; nt++) {
        int co0 = wn * 40 + nt * 8 + 2 * (lane & 3);
        float b0 = bias[co0], b1 = bias[co0 + 1];
        float sA = 0.f, qA = 0.f, sB = 0.f, qB = 0.f;
#pragma unroll
        for (int mt = 0; mt < 2; mt++) {
            float c0 = acc[mt][nt][0] + b0;
            float c1 = acc[mt][nt][1] + b1;
            float c2 = acc[mt][nt][2] + b0;
            float c3 = acc[mt][nt][3] + b1;
            int r = r0 + mt * 16;
            ybase[(size_t)co0 * S_TOT + r]           = c0;
            ybase[(size_t)(co0 + 1) * S_TOT + r]     = c1;
            ybase[(size_t)co0 * S_TOT + r + 8]       = c2;
            ybase[(size_t)(co0 + 1) * S_TOT + r + 8] = c3;
            sA += c0 + c2; qA += c0 * c0 + c2 * c2;
            sB += c1 + c3; qB += c1 * c1 + c3 * c3;
        }
#pragma unroll
        for (int o = 4; o < 32; o <<= 1) {
            sA += __shfl_xor_sync(0xffffffffu, sA, o);
            qA += __shfl_xor_sync(0xffffffffu, qA, o);
            sB += __shfl_xor_sync(0xffffffffu, sB, o);
            qB += __shfl_xor_sync(0xffffffffu, qB, o);
        }
        if (lane < 4) {
            atomicAdd(&d_sum[statbase + co0], sA);
            atomicAdd(&d_sumsq[statbase + co0], qA);
            atomicAdd(&d_sum[statbase + co0 + 1], sB);
            atomicAdd(&d_sumsq[statbase + co0 + 1], qB);
        }
    }
}

// ---------------------------------------------------------------------------
__global__ void finalize_stats() {
    int i = blockIdx.x * blockDim.x + threadIdx.x;
    if (i < 2 * NB * COUT) {
        float m   = d_sum[i] * (1.f / (float)S_TOT);
        float var = d_sumsq[i] * (1.f / (float)S_TOT) - m * m;
        d_mu[i]   = m;
        d_istd[i] = rsqrtf(var + 1e-5f);
    }
}

// ---------------------------------------------------------------------------
// Fused: normalize, ELU, sum, Wpsi-dot, sigmoid, out = x*psi.  float2/thread.
__global__ __launch_bounds__(256)
void fuse_gate(const float* __restrict__ x, const float* __restrict__ Wpsi,
               const float* __restrict__ bpsi, float* __restrict__ out)
{
    __shared__ float smug[COUT], ssig[COUT], smux[COUT], ssix[COUT], sw[COUT];
    const int n = blockIdx.y, tid = threadIdx.x;
    if (tid < COUT) {
        smug[tid] = d_mu[n * COUT + tid];
        ssig[tid] = d_istd[n * COUT + tid];
        smux[tid] = d_mu[(NB + n) * COUT + tid];
        ssix[tid] = d_istd[(NB + n) * COUT + tid];
        sw[tid]   = Wpsi[tid];
    }
    __syncthreads();

    const size_t s  = ((size_t)blockIdx.x * 256 + tid) * 2;
    const float* yg = d_y[0] + (size_t)n * COUT * S_TOT + s;
    const float* yx = d_y[1] + (size_t)n * COUT * S_TOT + s;
    const float* xn = x      + (size_t)n * CIN  * S_TOT + s;
    float*       on = out    + (size_t)n * CIN  * S_TOT + s;

    float acc0 = bpsi[0], acc1 = acc0;
#pragma unroll 8
    for (int c = 0; c < COUT; c++) {
        float2 a2 = *(const float2*)(yg + (size_t)c * S_TOT);
        float2 b2 = *(const float2*)(yx + (size_t)c * S_TOT);
        float mg = smug[c], ig = ssig[c], mx = smux[c], ix = ssix[c], w = sw[c];
        float a0 = (a2.x - mg) * ig; a0 = a0 > 0.f ? a0 : (__expf(a0) - 1.f);
        float a1 = (a2.y - mg) * ig; a1 = a1 > 0.f ? a1 : (__expf(a1) - 1.f);
        float b0 = (b2.x - mx) * ix; b0 = b0 > 0.f ? b0 : (__expf(b0) - 1.f);
        float b1 = (b2.y - mx) * ix; b1 = b1 > 0.f ? b1 : (__expf(b1) - 1.f);
        acc0 = fmaf(w, a0 + b0, acc0);
        acc1 = fmaf(w, a1 + b1, acc1);
    }
    const float psi0 = 1.f / (1.f + __expf(-acc0));
    const float psi1 = 1.f / (1.f + __expf(-acc1));

#pragma unroll 8
    for (int c = 0; c < CIN; c++) {
        float2 xv = *(const float2*)(xn + (size_t)c * S_TOT);
        *(float2*)(on + (size_t)c * S_TOT) = make_float2(xv.x * psi0, xv.y * psi1);
    }
}

// ---------------------------------------------------------------------------
extern "C" void kernel_launch(void* const* d_in, const int* in_sizes, int n_in,
                              void* d_out, int out_size)
{
    const float* g    = (const float*)d_in[0];
    const float* x    = (const float*)d_in[1];
    const float* Wg   = (const float*)d_in[2];
    const float* bg   = (const float*)d_in[3];
    const float* Wx   = (const float*)d_in[4];
    const float* bx   = (const float*)d_in[5];
    const float* Wpsi = (const float*)d_in[6];
    const float* bpsi = (const float*)d_in[7];
    float* out = (float*)d_out;

    cudaFuncSetAttribute(gemm_mma, cudaFuncAttributeMaxDynamicSharedMemorySize, SMEM_BYTES);

    prepack_W<<<(2 * NCHUNK * COUT * 20 + 255) / 256, 256>>>(Wg, Wx);
    zero_stats<<<2, 512>>>();

    dim3 gg(S_TOT / BM, NB);   // (2048, 2)
    gemm_mma<<<gg, 256, SMEM_BYTES>>>(g, bg, 0);
    gemm_mma<<<gg, 256, SMEM_BYTES>>>(x, bx, 1);

    finalize_stats<<<2, 512>>>();

    dim3 gf(S_TOT / 512, NB);  // (256, 2)
    fuse_gate<<<gf, 256>>>(x, Wpsi, bpsi, out);
}